// round 12
// baseline (speedup 1.0000x reference)
#include <cuda_runtime.h>

static constexpr int NPIX   = 256 * 256;     // pixels per batch
static constexpr int NBATCH = 16;
static constexpr int NBINS  = 64;
static constexpr int BPB    = 18;            // blocks per batch
static constexpr int NBLK   = BPB * NBATCH;  // 288 blocks = 2 per SM (296 cap) -> co-resident
static constexpr int TPB    = 1024;
static constexpr int OUT_N  = NBATCH * NBINS * NBINS;

// Shift-replicated packed histogram geometry:
// replica r stores bin b at word (b+r)>>2, 16-bit field (b+r)&3.
// Valid bin range written: -1..66 -> word index 0..16 -> 17 words/row.
static constexpr int ROWW = 17;              // u64 words per ref-row
static constexpr int REPW = NBINS * ROWW;    // words per replica (1088)
static constexpr int HWORDS = 4 * REPW;      // 4352 u64 = 34 KB

// Per-block min/max slots (plain overwrite each call -> no reset needed)
__device__ unsigned g_slot[NBLK][4];
// Monotone arrival counter (never reset; round target derived from own ticket)
__device__ unsigned g_cnt;

__device__ __forceinline__ unsigned fenc(float f) {
    unsigned b = __float_as_uint(f);
    return (b & 0x80000000u) ? ~b : (b | 0x80000000u);
}
__device__ __forceinline__ float fdec(unsigned e) {
    unsigned b = (e & 0x80000000u) ? (e & 0x7fffffffu) : ~e;
    return __uint_as_float(b);
}

// One pixel: 4x4 B-spline outer product. Tar window packed into ONE aligned
// u64 per ref row via the shift-replica trick -> exactly 4 smem atomics.
__device__ __forceinline__ void accum(float r, float t,
                                      float rmin, float rs,
                                      float tmin, float ts,
                                      unsigned long long* __restrict__ sh)
{
    float fr = (r - rmin) * rs;              // in [0, 64]
    float ft = (t - tmin) * ts;
    float fir = floorf(fr), fit = floorf(ft);
    float ur = fr - fir,   ut = ft - fit;
    int br = (int)fir - 1;                   // -1..63
    int bt = (int)fit - 1;                   // -1..63

    float vr = 1.0f - ur, vt = 1.0f - ut;
    float urr = ur * ur, vrr = vr * vr, utt = ut * ut, vtt = vt * vt;

    float wr[4];
    wr[0] = vrr * vr * (1.0f / 6.0f);
    wr[1] = fmaf(-urr, fmaf(-0.5f, ur, 1.0f), 2.0f / 3.0f);
    wr[2] = fmaf(-vrr, fmaf(-0.5f, vr, 1.0f), 2.0f / 3.0f);
    wr[3] = urr * ur * (1.0f / 6.0f);

    // tar weights pre-scaled by 4096 (= 1/EPS^2 folded into the fixed point)
    float wt0 = vtt * vt * (4096.0f / 6.0f);
    float wt1 = fmaf(-utt, fmaf(-0.5f, ut, 1.0f), 2.0f / 3.0f) * 4096.0f;
    float wt2 = fmaf(-vtt, fmaf(-0.5f, vt, 1.0f), 2.0f / 3.0f) * 4096.0f;
    float wt3 = utt * ut * (4096.0f / 6.0f);

    const float MAGIC = 12582912.0f;         // 1.5 * 2^23: round-to-nearest in mantissa
    int rep  = (-bt) & 3;                    // replica in which this window is aligned
    int word = (bt + rep) >> 2;              // 0..16
    unsigned long long* base = sh + rep * REPW + word;

    #pragma unroll
    for (int i = 0; i < 4; i++) {
        int bi = br + i;
        if ((unsigned)bi >= (unsigned)NBINS) continue;
        float w = wr[i];
        unsigned m0 = __float_as_uint(fmaf(w, wt0, MAGIC));
        unsigned m1 = __float_as_uint(fmaf(w, wt1, MAGIC));
        unsigned m2 = __float_as_uint(fmaf(w, wt2, MAGIC));
        unsigned m3 = __float_as_uint(fmaf(w, wt3, MAGIC));
        unsigned lo = __byte_perm(m0, m1, 0x5410);
        unsigned hi = __byte_perm(m2, m3, 0x5410);
        unsigned long long P = ((unsigned long long)hi << 32) | lo;
        atomicAdd(base + bi * ROWW, P);
    }
}

__global__ __launch_bounds__(TPB, 2)
void k_fused(const float4* __restrict__ ref,
             const float4* __restrict__ tar,
             float* __restrict__ out)
{
    __shared__ unsigned long long sh[HWORDS];   // 34 KB: 4 shift-replicas
    __shared__ unsigned s_mm[4];
    const int tid = threadIdx.x;
    const int bid = blockIdx.x;
    const int lane = tid & 31;

    // ---- phase 0: zero output slice + shared hist + smem minmax cells ----
    for (int i = bid * TPB + tid; i < OUT_N; i += NBLK * TPB) out[i] = 0.0f;
    for (int i = tid; i < HWORDS; i += TPB) sh[i] = 0ull;
    if (tid < 4) s_mm[tid] = (tid & 1) ? 0u : 0xFFFFFFFFu;

    // ---- phase 1: global min/max over both full images ----
    unsigned rmn = 0xFFFFFFFFu, rmx = 0u, tmn = 0xFFFFFFFFu, tmx = 0u;
    const int n4 = NBATCH * NPIX / 4;
    for (int i = bid * TPB + tid; i < n4; i += NBLK * TPB) {
        float4 a = ref[i];
        unsigned e;
        e = fenc(a.x); rmn = min(rmn, e); rmx = max(rmx, e);
        e = fenc(a.y); rmn = min(rmn, e); rmx = max(rmx, e);
        e = fenc(a.z); rmn = min(rmn, e); rmx = max(rmx, e);
        e = fenc(a.w); rmn = min(rmn, e); rmx = max(rmx, e);
        float4 b = tar[i];
        e = fenc(b.x); tmn = min(tmn, e); tmx = max(tmx, e);
        e = fenc(b.y); tmn = min(tmn, e); tmx = max(tmx, e);
        e = fenc(b.z); tmn = min(tmn, e); tmx = max(tmx, e);
        e = fenc(b.w); tmn = min(tmn, e); tmx = max(tmx, e);
    }
    #pragma unroll
    for (int o = 16; o > 0; o >>= 1) {
        rmn = min(rmn, __shfl_xor_sync(0xFFFFFFFFu, rmn, o));
        rmx = max(rmx, __shfl_xor_sync(0xFFFFFFFFu, rmx, o));
        tmn = min(tmn, __shfl_xor_sync(0xFFFFFFFFu, tmn, o));
        tmx = max(tmx, __shfl_xor_sync(0xFFFFFFFFu, tmx, o));
    }
    __syncthreads();
    if (lane == 0) {
        atomicMin(&s_mm[0], rmn); atomicMax(&s_mm[1], rmx);
        atomicMin(&s_mm[2], tmn); atomicMax(&s_mm[3], tmx);
    }
    __threadfence();                       // release: out-zero stores visible
    __syncthreads();

    // ---- grid sync (288 CTAs, 2 per SM, single wave -> co-resident) ----
    if (tid == 0) {
        volatile unsigned* sl = g_slot[bid];
        sl[0] = s_mm[0]; sl[1] = s_mm[1]; sl[2] = s_mm[2]; sl[3] = s_mm[3];
        __threadfence();
        unsigned prev = atomicAdd(&g_cnt, 1);
        unsigned target = prev - (prev % NBLK) + NBLK;   // end of this round
        while (*(volatile unsigned*)&g_cnt < target) { }
        __threadfence();                   // acquire
    }
    __syncthreads();

    // ---- reduce all block slots -> global min/max ----
    if (tid < 4) s_mm[tid] = (tid & 1) ? 0u : 0xFFFFFFFFu;
    __syncthreads();
    if (tid < NBLK) {
        volatile unsigned* sl = g_slot[tid];
        unsigned a0 = sl[0], a1 = sl[1], a2 = sl[2], a3 = sl[3];
        atomicMin(&s_mm[0], a0); atomicMax(&s_mm[1], a1);
        atomicMin(&s_mm[2], a2); atomicMax(&s_mm[3], a3);
    }
    __syncthreads();

    const float rmin = fdec(s_mm[0]), rmax = fdec(s_mm[1]);
    const float tmin = fdec(s_mm[2]), tmax = fdec(s_mm[3]);
    const float rs = 64.0f / (rmax - rmin);
    const float ts = 64.0f / (tmax - tmin);

    // ---- phase 2: per-batch joint histogram (images now L2-resident) ----
    const int batch = bid / BPB, sub = bid % BPB;
    const float4* rp = ref + (size_t)batch * (NPIX / 4);
    const float4* tp = tar + (size_t)batch * (NPIX / 4);
    for (int i = sub * TPB + tid; i < NPIX / 4; i += BPB * TPB) {
        float4 r4 = rp[i];
        float4 t4 = tp[i];
        accum(r4.x, t4.x, rmin, rs, tmin, ts, sh);
        accum(r4.y, t4.y, rmin, rs, tmin, ts, sh);
        accum(r4.z, t4.z, rmin, rs, tmin, ts, sh);
        accum(r4.w, t4.w, rmin, rs, tmin, ts, sh);
    }
    __syncthreads();

    // ---- phase 3: combine 4 replicas, unpack (scale 4096 = 1/EPS^2), flush ----
    float* o = out + (size_t)batch * NBINS * NBINS;
    for (int c = tid; c < NBINS * NBINS; c += TPB) {
        int row = c >> 6;
        int bt  = c & 63;
        unsigned acc = 0;
        #pragma unroll
        for (int r = 0; r < 4; r++) {
            int w = (bt + r) >> 2;
            int f = (bt + r) & 3;
            unsigned long long h = sh[r * REPW + row * ROWW + w];
            acc += (unsigned)(h >> (f * 16)) & 0xFFFFu;
        }
        atomicAdd(&o[c], (float)acc);
    }
}

extern "C" void kernel_launch(void* const* d_in, const int* in_sizes, int n_in,
                              void* d_out, int out_size) {
    const float4* img_ref = (const float4*)d_in[0];
    const float4* img_tar = (const float4*)d_in[1];
    float* out = (float*)d_out;
    k_fused<<<NBLK, TPB>>>(img_ref, img_tar, out);
}